// round 17
// baseline (speedup 1.0000x reference)
#include <cuda_runtime.h>
#include <cstdint>

// ---------------- problem constants ----------------
#define NN 65536
#define DD 1024
#define KM 64
#define NBLK 128
typedef unsigned long long ull;

// ---------------- device state ----------------
__device__ float  g_x2[NN];
__device__ float  g_dmin[NN];
__device__ int    g_ztmp[NN];
__device__ float  g_m2[KM];
__device__ float  g_colpart2[NBLK][DD];
__device__ float  g_objA[64];
__device__ float  g_objF[NBLK];
__device__ float  g_sumpart[8][64][KM][128];   // [dchunk][pblk][k][dsub]
__device__ int    g_counts[KM];
__device__ int    g_anyfar;
__device__ int    g_K, g_done;
__device__ double g_prev;
__device__ unsigned g_barcnt;
__device__ volatile unsigned g_bargen;

// ---------------- helpers ----------------
__device__ __forceinline__ ull pk2(float a, float b) {
    ull r; asm("mov.b64 %0, {%1,%2};" : "=l"(r) : "f"(a), "f"(b)); return r;
}
__device__ __forceinline__ void fma2(ull &acc, ull a, ull b) {
    asm("fma.rn.f32x2 %0, %1, %2, %0;" : "+l"(acc) : "l"(a), "l"(b));
}
__device__ __forceinline__ void un2(ull v, float &x, float &y) {
    asm("mov.b64 {%0,%1}, %2;" : "=f"(x), "=f"(y) : "l"(v));
}
__device__ __forceinline__ void cpa16(uint32_t dst, const float* src) {
    asm volatile("cp.async.cg.shared.global [%0], [%1], 16;\n" :: "r"(dst), "l"(src));
}
__device__ __forceinline__ void cpa_commit() {
    asm volatile("cp.async.commit_group;\n" ::: "memory");
}
template<int N> __device__ __forceinline__ void cpa_wait() {
    asm volatile("cp.async.wait_group %0;\n" :: "n"(N) : "memory");
}
__device__ __forceinline__ float vldf(const float* p) { return *(volatile const float*)p; }
__device__ __forceinline__ int   vldi(const int* p)   { return *(volatile const int*)p; }

// grid-wide barrier: all NBLK blocks resident (1 block/SM, 128 <= 148 SMs)
__device__ __forceinline__ void gbar(unsigned &gen) {
    __syncthreads();
    if (threadIdx.x == 0) {
        gen++;
        __threadfence();
        unsigned t = atomicAdd(&g_barcnt, 1);
        if (t == NBLK - 1) {
            g_barcnt = 0;
            __threadfence();
            g_bargen = gen;
        } else {
            while (g_bargen < gen) { __nanosleep(64); }
            __threadfence();
        }
    }
    __syncthreads();
}

// ---------------- tiny reset kernel (per replay) ----------------
__global__ void kI0() {
    int tid = threadIdx.x;
    if (tid < KM) g_counts[tid] = 0;
    if (tid == 0) {
        g_K = 1; g_done = 0; g_prev = 0.0; g_anyfar = 0;
        g_barcnt = 0; g_bargen = 0;
    }
}

// ---------------- persistent mega-kernel ----------------
// P0: x2 (bit-identical to old kI1 order) + column partials, one X pass
// P1: mu[0] = mean, zero rows 1..63, m2
// per iteration (4 grid barriers):
//  A  : warp-autonomous fused GEMM (8-wide k-passes, per-warp cp.async ring,
//       no block syncs in the 64-stage loop) + masked min/argmin + anyfar
//  C2 : vectorized scatter-sum partials + counts + non-cf obj partials
//  DF : centroid update + m2; nc rebuild + cf dvals (create iters)
//  G  : obj reduce (double), convergence, commit scalars
__global__ __launch_bounds__(256) void kMega(const float* __restrict__ X, float* __restrict__ mu) {
    // A: X ring 8 warps x 3 slots x 64 rows x pitch20 = 30720 floats,
    //    B8 = 8 clusters x 1024 dims = 8192 floats  -> 38912 floats (~152 KB)
    __shared__ __align__(16) float sraw[38976];
    const int tid = threadIdx.x, bid = blockIdx.x;
    const int w = tid >> 5, lane = tid & 31;
    unsigned gen = 0;

    const int pbase = bid * 512;
    float* sXw = sraw + w * 3840;          // this warp's 3-slot ring (1280 floats/slot)
    float* sB8 = sraw + 30720;             // [8][1024]
    const uint32_t sxw0 = (uint32_t)__cvta_generic_to_shared(sXw);
    const uint32_t sb8  = (uint32_t)__cvta_generic_to_shared(sB8);

    // per-lane X copy plan (warp-local rows, constant for whole kernel)
    const float* Xw[8]; uint32_t dxw[8];
#pragma unroll
    for (int j = 0; j < 8; j++) {
        int c = lane + 32 * j;
        int row = c >> 2, q = c & 3;
        Xw[j]  = X + (size_t)(pbase + 64 * w + row) * DD + 4 * q;
        dxw[j] = sxw0 + (uint32_t)(row * 80 + 16 * q);
    }
    const int p0 = 64 * w + lane;

    // ===================== P0: x2 + column partials =====================
    {
        float* sacc = sraw;              // [8][1024]
        float racc[32];
#pragma unroll
        for (int j = 0; j < 32; j++) racc[j] = 0.f;
        const float* rowbase = X + (size_t)(pbase + 64 * w) * DD;
        for (int t = 0; t < 64; t++) {
            const float* row = rowbase + (size_t)t * DD;
            float s = 0.f;
#pragma unroll
            for (int j = 0; j < 32; j++) {
                float v = row[lane + 32 * j];
                racc[j] += v;
                s = fmaf(v, v, s);
            }
#pragma unroll
            for (int off = 16; off > 0; off >>= 1) s += __shfl_xor_sync(0xFFFFFFFFu, s, off);
            if (lane == 0) g_x2[pbase + 64 * w + t] = s;
        }
#pragma unroll
        for (int j = 0; j < 32; j++) sacc[w * 1024 + lane + 32 * j] = racc[j];
        __syncthreads();
#pragma unroll
        for (int jj = 0; jj < 4; jj++) {
            int d = tid + 256 * jj;
            float s = 0.f;
#pragma unroll
            for (int ww = 0; ww < 8; ww++) s += sacc[ww * 1024 + d];
            g_colpart2[bid][d] = s;
        }
    }
    gbar(gen);

    // ===================== P1: mu0 / zero rows / m2 =====================
    if (bid == 0) {
        float* smr = sraw;
        float ss = 0.f;
#pragma unroll
        for (int jj = 0; jj < 4; jj++) {
            int d = tid + 256 * jj;
            float s = 0.f;
#pragma unroll 8
            for (int b = 0; b < NBLK; b++) s += vldf(&g_colpart2[b][d]);
            float m = s * (1.0f / 65536.0f);
            mu[d] = m;
            ss = fmaf(m, m, ss);
        }
        smr[tid] = ss;
        __syncthreads();
        for (int off = 128; off > 0; off >>= 1) { if (tid < off) smr[tid] += smr[tid + off]; __syncthreads(); }
        if (tid == 0) g_m2[0] = smr[0];
    } else if (bid < 64) {
#pragma unroll
        for (int jj = 0; jj < 4; jj++) mu[(size_t)bid * DD + tid + 256 * jj] = 0.f;
        if (tid == 0) g_m2[bid] = 0.f;
    }
    gbar(gen);

    const float x2r0 = vldf(g_x2 + pbase + p0);
    const float x2r1 = vldf(g_x2 + pbase + p0 + 32);

    for (int iter = 0; iter < 50; ++iter) {
        if (vldi(&g_done)) break;
        const int K = vldi(&g_K);

        // ===================== Phase A (warp-autonomous) =====================
        const int kcols = (K + 7) & ~7;          // 8-wide padding
        float best0 = 3.0e38f, best1 = 3.0e38f;
        int bidx0 = 0, bidx1 = 0;

        for (int kbase = 0; kbase < kcols; kbase += 8) {
            // --- B preload: 8 clusters, full rows (block-cooperative) ---
            __syncthreads();
#pragma unroll
            for (int j = 0; j < 8; j++) {
                int c = tid + 256 * j;
                cpa16(sb8 + (uint32_t)(16 * c),
                      mu + (size_t)(kbase + (c >> 8)) * DD + 4 * (c & 255));
            }
            cpa_commit();
            cpa_wait<0>();
            __syncthreads();

            ull a0[4], a1[4];
#pragma unroll
            for (int m = 0; m < 4; m++) { a0[m] = 0ull; a1[m] = 0ull; }

            // --- per-warp X prologue: stages 0,1 ---
#pragma unroll
            for (int s = 0; s < 2; s++) {
#pragma unroll
                for (int j = 0; j < 8; j++) cpa16(dxw[j] + (uint32_t)(s * 5120), Xw[j] + s * 16);
                cpa_commit();
            }

            // --- 64-stage warp-local pipeline (no block syncs) ---
            for (int s = 0; s < 64; ++s) {
                cpa_wait<1>();
                __syncwarp();
                if (s < 62) {
                    const int sn = s + 2;
                    const uint32_t ox = (uint32_t)((sn % 3) * 5120);
#pragma unroll
                    for (int j = 0; j < 8; j++) cpa16(dxw[j] + ox, Xw[j] + sn * 16);
                }
                cpa_commit();           // empty at tail keeps FIFO accounting sound
                {
                    const int sl = s % 3;
                    const float* xb0 = sXw + sl * 1280 + lane * 20;
                    const float* xb1 = xb0 + 640;
                    const float* bb = sB8 + s * 16;
#pragma unroll
                    for (int q = 0; q < 4; q++) {
                        float4 x0 = *reinterpret_cast<const float4*>(xb0 + 4 * q);
                        float4 x1 = *reinterpret_cast<const float4*>(xb1 + 4 * q);
                        ull xp0[4], xp1[4];
                        xp0[0] = pk2(x0.x, x0.x); xp0[1] = pk2(x0.y, x0.y);
                        xp0[2] = pk2(x0.z, x0.z); xp0[3] = pk2(x0.w, x0.w);
                        xp1[0] = pk2(x1.x, x1.x); xp1[1] = pk2(x1.y, x1.y);
                        xp1[2] = pk2(x1.z, x1.z); xp1[3] = pk2(x1.w, x1.w);
#pragma unroll
                        for (int m = 0; m < 4; m++) {
                            float4 bA  = *reinterpret_cast<const float4*>(bb + (2 * m) * 1024 + 4 * q);
                            float4 bBv = *reinterpret_cast<const float4*>(bb + (2 * m + 1) * 1024 + 4 * q);
                            ull bp0 = pk2(bA.x, bBv.x), bp1 = pk2(bA.y, bBv.y);
                            ull bp2 = pk2(bA.z, bBv.z), bp3 = pk2(bA.w, bBv.w);
                            fma2(a0[m], xp0[0], bp0); fma2(a0[m], xp0[1], bp1);
                            fma2(a0[m], xp0[2], bp2); fma2(a0[m], xp0[3], bp3);
                            fma2(a1[m], xp1[0], bp0); fma2(a1[m], xp1[1], bp1);
                            fma2(a1[m], xp1[2], bp2); fma2(a1[m], xp1[3], bp3);
                        }
                    }
                }
            }

            // --- epilogue for this 8-wide k-pass (ascending k => first-index ties) ---
#pragma unroll
            for (int m = 0; m < 4; m++) {
                int k0 = kbase + 2 * m;
                float m2a = vldf(g_m2 + k0), m2b = vldf(g_m2 + k0 + 1);
                float s0, s1; un2(a0[m], s0, s1);
                float d0 = fmaf(-2.f, s0, x2r0) + m2a;
                float d1 = fmaf(-2.f, s1, x2r0) + m2b;
                if (k0 < K && d0 < best0) { best0 = d0; bidx0 = k0; }
                if (k0 + 1 < K && d1 < best0) { best0 = d1; bidx0 = k0 + 1; }
                un2(a1[m], s0, s1);
                float e0 = fmaf(-2.f, s0, x2r1) + m2a;
                float e1 = fmaf(-2.f, s1, x2r1) + m2b;
                if (k0 < K && e0 < best1) { best1 = e0; bidx1 = k0; }
                if (k0 + 1 < K && e1 < best1) { best1 = e1; bidx1 = k0 + 1; }
            }
        }

        g_dmin[pbase + p0] = best0;       g_ztmp[pbase + p0] = bidx0;
        g_dmin[pbase + p0 + 32] = best1;  g_ztmp[pbase + p0 + 32] = bidx1;
        {
            bool farflag = (best0 > 1000.f) || (best1 > 1000.f);
            unsigned b = __ballot_sync(0xFFFFFFFFu, farflag);
            if (b && lane == 0) atomicOr(&g_anyfar, 1);
        }
        gbar(gen);

        // ------- iteration bookkeeping (uniform across blocks) -------
        const int create = (vldi(&g_anyfar) != 0) && (K < KM);
        const int Kc = K;
        const int Knew = K + create;
        const int kmax = min(KM, (Knew + 15) & ~15);
        const int nk2 = kmax >> 4;

        // ===================== Phase C2 =====================
        {
            const int h = tid >> 7, t128 = tid & 127;
            float4* acc4 = reinterpret_cast<float4*>(sraw) + h * 2048;
            int* zsh  = reinterpret_cast<int*>(sraw + 16384) + h * 1024;
            int* scnt = reinterpret_cast<int*>(sraw + 18432);
            float* ored = sraw + 18496;
            if (bid < 64 && tid < 64) scnt[tid] = 0;
            float objs = 0.f;
            const int c = t128 & 31, pg = t128 >> 5;

            for (int jo = 0; jo < 2; jo++) {
                const int unit = (jo * 2 + h) * 128 + bid;
                const int dchunk = unit >> 6, pblk = unit & 63;
                const int dbase = dchunk * 128, pb = pblk * 1024;
                const bool docount = (jo == 0) && (h == 0) && (bid < 64);
                __syncthreads();
#pragma unroll
                for (int q = 0; q < 8; q++) {
                    int ip = pb + q * 128 + t128;
                    float dmv = vldf(g_dmin + ip);
                    int ztv = vldi(g_ztmp + ip);
                    bool cf = create && (dmv > 1000.f);
                    int z = cf ? Kc : ztv;
                    zsh[q * 128 + t128] = z;
                    if (docount) { atomicAdd(&scnt[z], 1); if (!cf) objs += dmv; }
                }
                const float* xp = X + (size_t)(pb + pg * 256) * DD + dbase + 4 * c;
                for (int kg2 = 0; kg2 < nk2; kg2++) {
                    __syncthreads();
#pragma unroll
                    for (int kk = 0; kk < 16; kk++)
                        acc4[(pg * 16 + kk) * 32 + c] = make_float4(0.f, 0.f, 0.f, 0.f);
                    __syncthreads();
#pragma unroll 4
                    for (int t = 0; t < 256; t++) {
                        float4 v = *reinterpret_cast<const float4*>(xp + (size_t)t * DD);
                        int zr = zsh[pg * 256 + t] - (kg2 << 4);
                        if ((unsigned)zr < 16u) {
                            float4 a = acc4[(pg * 16 + zr) * 32 + c];
                            a.x += v.x; a.y += v.y; a.z += v.z; a.w += v.w;
                            acc4[(pg * 16 + zr) * 32 + c] = a;
                        }
                    }
                    __syncthreads();
#pragma unroll
                    for (int kb = 0; kb < 16; kb += 4) {
                        int kloc = kb + (t128 >> 5);
                        float4 s0 = acc4[(0 * 16 + kloc) * 32 + c];
                        float4 s1 = acc4[(1 * 16 + kloc) * 32 + c];
                        float4 s2 = acc4[(2 * 16 + kloc) * 32 + c];
                        float4 s3 = acc4[(3 * 16 + kloc) * 32 + c];
                        float4 o;
                        o.x = ((s0.x + s1.x) + s2.x) + s3.x;
                        o.y = ((s0.y + s1.y) + s2.y) + s3.y;
                        o.z = ((s0.z + s1.z) + s2.z) + s3.z;
                        o.w = ((s0.w + s1.w) + s2.w) + s3.w;
                        *reinterpret_cast<float4*>(&g_sumpart[dchunk][pblk][kg2 * 16 + kloc][4 * c]) = o;
                    }
                }
            }
            __syncthreads();
            if (bid < 64) {
                ored[tid] = (h == 0) ? objs : 0.f;
                __syncthreads();
                for (int off = 128; off > 0; off >>= 1) { if (tid < off) ored[tid] += ored[tid + off]; __syncthreads(); }
                if (tid == 0) g_objA[bid] = ored[0];
                if (tid < 64 && scnt[tid]) atomicAdd(&g_counts[tid], scnt[tid]);
            }
        }
        gbar(gen);

        // ===================== Phase D+F =====================
        if (bid < Knew) {
            float* smr = sraw + 2048;
            const int k = bid;
            const int cnt = vldi(g_counts + k);
            float ss = 0.f;
#pragma unroll
            for (int jo2 = 0; jo2 < 4; jo2++) {
                int d = tid + 256 * jo2;
                float s = 0.f;
#pragma unroll 8
                for (int pb2 = 0; pb2 < 64; pb2++)
                    s += vldf(&g_sumpart[d >> 7][pb2][k][d & 127]);
                float mv;
                if (cnt > 0) { mv = s / (float)cnt; mu[(size_t)k * DD + d] = mv; }
                else mv = vldf(&mu[(size_t)k * DD + d]);
                ss = fmaf(mv, mv, ss);
            }
            smr[tid] = ss;
            __syncthreads();
            for (int off = 128; off > 0; off >>= 1) { if (tid < off) smr[tid] += smr[tid + off]; __syncthreads(); }
            if (tid == 0) g_m2[k] = smr[0];
        }
        if (create) {
            float* snc = sraw;           // 1024
            float* wred = sraw + 1088;   // 8
            const int cntc = vldi(g_counts + Kc);
#pragma unroll
            for (int jo2 = 0; jo2 < 4; jo2++) {
                int d = tid + 256 * jo2;
                float s = 0.f;
#pragma unroll 8
                for (int pb2 = 0; pb2 < 64; pb2++)
                    s += vldf(&g_sumpart[d >> 7][pb2][Kc][d & 127]);
                snc[d] = s / (float)cntc;      // == mu[Kc][d] bit-identical
            }
            __syncthreads();
            float objw = 0.f;
            for (int t = 0; t < 64; t++) {
                int i = pbase + w * 64 + t;
                float dmv = vldf(g_dmin + i);
                if (dmv > 1000.f) {
                    const float* row = X + (size_t)i * DD;
                    float s = 0.f;
#pragma unroll
                    for (int j = 0; j < 32; j++) {
                        int d = lane + 32 * j;
                        float dv = row[d] - snc[d];
                        s = fmaf(dv, dv, s);
                    }
#pragma unroll
                    for (int off = 16; off > 0; off >>= 1) s += __shfl_xor_sync(0xFFFFFFFFu, s, off);
                    objw += s;
                }
            }
            if (lane == 0) wred[w] = objw;
            __syncthreads();
            if (tid == 0) {
                float s = 0.f;
                for (int q = 0; q < 8; q++) s += wred[q];
                g_objF[bid] = s;
            }
        } else if (tid == 0) g_objF[bid] = 0.f;
        gbar(gen);

        // ===================== Phase G =====================
        if (bid == 0) {
            double* sd = reinterpret_cast<double*>(sraw);
            double v = 0.0;
            if (tid < 64) v += (double)vldf(g_objA + tid);
            if (tid >= 64 && tid < 64 + NBLK) v += (double)vldf(g_objF + (tid - 64));
            sd[tid] = v;
            __syncthreads();
            for (int off = 128; off > 0; off >>= 1) { if (tid < off) sd[tid] += sd[tid + off]; __syncthreads(); }
            if (tid == 0) {
                double obj = sd[0] + 1000.0 * (double)Knew;
                bool conv = (iter > 0) && (fabs(obj - g_prev) < 1e-3 * obj);
                g_prev = obj;
                *(volatile int*)&g_K = Knew;
                *(volatile int*)&g_anyfar = 0;
                if (conv) *(volatile int*)&g_done = 1;
            }
            if (tid < 64) *(volatile int*)(g_counts + tid) = 0;
        }
        gbar(gen);
    }
}

// ---------------- launch ----------------
extern "C" void kernel_launch(void* const* d_in, const int* in_sizes, int n_in,
                              void* d_out, int out_size) {
    const float* X = (const float*)d_in[0];
    float* mu = (float*)d_out;   // d_out (1,64,1024) doubles as the live centroid buffer

    kI0<<<1, 256>>>();
    kMega<<<NBLK, 256>>>(X, mu);
}